// round 6
// baseline (speedup 1.0000x reference)
#include <cuda_runtime.h>
#include <cstdint>

#define BB 8
#define SS 8192
#define NTOK (BB * SS)
#define NCHUNK 64          // 1024-token chunks, 8 per row
#define TOKC 2048          // tokens per embed block
#define SLICES 16

typedef unsigned long long u64;

// Per-token packed word:
//   bits [0,48)  : addr one-hot (lo/hi/top nibbles)
//   bit 48: THINK_START(456)  bit 49: THINK_END(457)  bit 50: MEM_EXEC(458)
//   bits [52,61) : token id (0..271)
__device__ u64 g_mask[NTOK];
__device__ int g_chunk_cs[NCHUNK];   // row-relative pos of last CODE_START in chunk, or -1
__device__ int g_chunk_ce[NCHUNK];   // row-relative pos of first CODE_END in chunk, or SS

// ---------------------------------------------------------------------------
// Kernel A: per-chunk summaries. 64 blocks x 256 threads, 4 tokens/thread.
// ---------------------------------------------------------------------------
__global__ void __launch_bounds__(256) nvm_sum_kernel(const int* __restrict__ tok) {
    __shared__ int w_cs[8], w_ce[8];
    int tid = threadIdx.x;
    int lane = tid & 31, wid = tid >> 5;

    int4 v = reinterpret_cast<const int4*>(tok)[blockIdx.x * 256 + tid];
    int p = ((blockIdx.x * 256 + tid) * 4) & (SS - 1);   // row-relative pos

    int cs = -1, ce = SS;
    int t[4] = {v.x, v.y, v.z, v.w};
#pragma unroll
    for (int i = 0; i < 4; i++) {
        if (t[i] == 256) cs = p + i;
        if (t[i] == 257 && (p + i) < ce) ce = p + i;
    }
#pragma unroll
    for (int off = 16; off > 0; off >>= 1) {
        int oc = __shfl_down_sync(0xffffffffu, cs, off);
        int oe = __shfl_down_sync(0xffffffffu, ce, off);
        if (oc > cs) cs = oc;
        if (oe < ce) ce = oe;
    }
    if (lane == 0) { w_cs[wid] = cs; w_ce[wid] = ce; }
    __syncthreads();
    if (tid == 0) {
        int bc = -1, be = SS;
#pragma unroll
        for (int i = 0; i < 8; i++) {
            if (w_cs[i] > bc) bc = w_cs[i];
            if (w_ce[i] < be) be = w_ce[i];
        }
        g_chunk_cs[blockIdx.x] = bc;
        g_chunk_ce[blockIdx.x] = be;
    }
}

// ---------------------------------------------------------------------------
// Kernel B: mask computation. 64 blocks x 256 threads, 4 tokens/thread.
// Intra-chunk shuffle scan + cross-chunk prefix from summaries.
// ---------------------------------------------------------------------------
__global__ void __launch_bounds__(256) nvm_mask_kernel(const int* __restrict__ tok) {
    __shared__ int sh[1032];           // 8 halo + 1024 chunk tokens
    __shared__ int warp_part[8];
    __shared__ int s_prev_cs, s_fce;

    int c = blockIdx.x;                // global chunk
    int b = c >> 3;
    int ci = c & 7;                    // chunk within row
    int chunkbase = ci * 1024;         // row-relative
    const int* row = tok + b * SS;
    int tid = threadIdx.x;
    int lane = tid & 31, wid = tid >> 5;

    reinterpret_cast<int4*>(sh + 8)[tid] =
        reinterpret_cast<const int4*>(row + chunkbase)[tid];
    if (tid < 8) sh[tid] = (ci > 0) ? row[chunkbase - 8 + tid] : -1;

    if (tid == 0) {
        int p = -1, f = SS;
#pragma unroll
        for (int j = 0; j < 8; j++) {
            int cs = g_chunk_cs[b * 8 + j];
            int ce = g_chunk_ce[b * 8 + j];
            if (j < ci && cs > p) p = cs;
            if (ce < f) f = ce;
        }
        s_prev_cs = p; s_fce = f;
    }
    __syncthreads();

    int lbase = tid * 4;               // local pos of first own token
    // own tokens + local cummax (row-relative positions)
    int tv[4], vals[4];
    int run = -1;
#pragma unroll
    for (int i = 0; i < 4; i++) {
        int t = sh[8 + lbase + i];
        tv[i] = t;
        if (t == 256) run = chunkbase + lbase + i;
        vals[i] = run;
    }
    // warp inclusive max-scan
    int v = run;
#pragma unroll
    for (int off = 1; off < 32; off <<= 1) {
        int o = __shfl_up_sync(0xffffffffu, v, off);
        if (lane >= off && o > v) v = o;
    }
    if (lane == 31) warp_part[wid] = v;
    __syncthreads();
    if (wid == 0 && lane < 8) {
        int w = warp_part[lane];
#pragma unroll
        for (int off = 1; off < 8; off <<= 1) {
            int o = __shfl_up_sync(0x000000ffu, w, off);
            if (lane >= off && o > w) w = o;
        }
        warp_part[lane] = w;
    }
    __syncthreads();

    int warp_prefix = (wid == 0) ? -1 : warp_part[wid - 1];
    int excl = __shfl_up_sync(0xffffffffu, v, 1);
    if (lane == 0) excl = -1;
    int prefix = (excl > warp_prefix) ? excl : warp_prefix;
    if (s_prev_cs > prefix) prefix = s_prev_cs;
    int fce = s_fce;

    u64 out[4];
#pragma unroll
    for (int i = 0; i < 4; i++) {
        int s = chunkbase + lbase + i;         // row-relative
        int t = tv[i];
        int cs = (vals[i] > prefix) ? vals[i] : prefix;

        u64 m = ((u64)t) << 52;
        if (t == 259) m |= (1ull << 48);
        if (t == 260) m |= (1ull << 49);
        if (t == 258 && (s + 8) < SS) m |= (1ull << 50);

        if (cs >= 0 && s < fce && t < 256) {
            int seq = s - cs - 1;
            int bo  = seq & 7;
            if (seq >= 0 && bo < 5) {
                int addr = (((seq >> 3) << 3) + 2 + bo) & 4095;
                m |= (1ull << (addr & 15))
                   | (1ull << (16 + ((addr >> 4) & 15)))
                   | (1ull << (32 + ((addr >> 8) & 15)));
            }
        }
        // mem look-back: jg = s-5-off (row-relative); sh idx = jg-chunkbase+8
#pragma unroll
        for (int off = 0; off < 4; off++) {
            int jg = s - 5 - off;
            if (jg >= 0 && (jg + 8) < SS) {
                int ji = jg - chunkbase + 8;
                if (sh[ji] == 258) {
                    int a = ((sh[ji + 1] | (sh[ji + 2] << 8)) + off) & 4095;
                    m |= (1ull << (a & 15))
                       | (1ull << (16 + ((a >> 4) & 15)))
                       | (1ull << (32 + ((a >> 8) & 15)));
                }
            }
        }
        out[i] = m;
    }

    ulonglong2* gm2 =
        reinterpret_cast<ulonglong2*>(&g_mask[b * SS + chunkbase + lbase]);
    gm2[0] = make_ulonglong2(out[0], out[1]);
    gm2[1] = make_ulonglong2(out[2], out[3]);
}

// ---------------------------------------------------------------------------
// Kernel C: dim-sliced embed. blockIdx.y = 32-dim slice, blockIdx.x = 2048-tok
// chunk. Table slice (34 KB) in SMEM; masks streamed via __ldg (L2-hot).
// 512 threads, 4 blocks/SM -> 100% occupancy, single wave (512 blocks).
// ---------------------------------------------------------------------------
__device__ __forceinline__ void apply_mask(float4& v, u64 m, int glane) {
    if (glane >= 51 && glane <= 63) {
        int d0 = glane << 2;
        float* vp = reinterpret_cast<float*>(&v);
#pragma unroll
        for (int c = 0; c < 4; c++) {
            int d = d0 + c;
            if (d >= 206 && d < 254 && ((m >> (d - 206)) & 1ull)) vp[c] = 1.0f;
        }
    } else if (glane == 114) {
        if ((m >> 48) & 1ull) v.x = 1.0f;   // 456
        if ((m >> 49) & 1ull) v.y = 1.0f;   // 457
        if ((m >> 50) & 1ull) v.z = 1.0f;   // 458
    }
}

__global__ void __launch_bounds__(512, 4) nvm_embed_kernel(
    const float4* __restrict__ tbl4,          // [272 * 128]
    float4* __restrict__ out4)                // [NTOK * 128]
{
    __shared__ float4 stbl[272 * 8];          // 34 KB table slice

    int sl = blockIdx.y;
    int tokbase = blockIdx.x * TOKC;
    int tid = threadIdx.x;

#pragma unroll
    for (int i = tid; i < 272 * 8; i += 512) {
        int r = i >> 3, l = i & 7;
        stbl[i] = __ldg(&tbl4[r * 128 + sl * 8 + l]);
    }
    __syncthreads();

    int l = tid & 7;                  // lane within slice
    int g = tid >> 3;                 // token group 0..63
    int glane = sl * 8 + l;
    bool needmask = (sl == 6) | (sl == 7) | (sl == 14);

    const u64* mp = g_mask + tokbase + g;
    float4* outp = out4 + (size_t)(tokbase + g) * 128 + glane;

    if (needmask) {
#pragma unroll 8
        for (int k = 0; k < TOKC / 64; k++) {
            u64 m = __ldg(mp + 64 * k);
            float4 v = stbl[((int)(m >> 52) & 511) * 8 + l];
            apply_mask(v, m, glane);
            __stcs(outp + (size_t)(64 * k) * 128, v);
        }
    } else {
#pragma unroll 8
        for (int k = 0; k < TOKC / 64; k++) {
            u64 m = __ldg(mp + 64 * k);
            float4 v = stbl[((int)(m >> 52) & 511) * 8 + l];
            __stcs(outp + (size_t)(64 * k) * 128, v);
        }
    }
}

// ---------------------------------------------------------------------------
extern "C" void kernel_launch(void* const* d_in, const int* in_sizes, int n_in,
                              void* d_out, int out_size) {
    const float* tbl;
    const int* tok;
    if (in_sizes[0] == 272 * 512) {
        tbl = (const float*)d_in[0];
        tok = (const int*)d_in[1];
    } else {
        tbl = (const float*)d_in[1];
        tok = (const int*)d_in[0];
    }
    float* out = (float*)d_out;

    nvm_sum_kernel<<<NCHUNK, 256>>>(tok);
    nvm_mask_kernel<<<NCHUNK, 256>>>(tok);

    dim3 grid(NTOK / TOKC, SLICES);   // (32, 16) = 512 blocks
    nvm_embed_kernel<<<grid, 512>>>((const float4*)tbl, (float4*)out);
}

// round 7
// speedup vs baseline: 1.2734x; 1.2734x over previous
#include <cuda_runtime.h>
#include <cstdint>

#define BB 8
#define SS 8192
#define NTOK (BB * SS)
#define TOKC 4096
#define NCH (NTOK / TOKC)      // 16 token chunks
#define SLICES 16

typedef unsigned long long u64;
typedef unsigned int u32;
typedef unsigned short u16;

// dynamic smem layout (bytes):
//   [0,      34816)  float4 stbl[272*8]   table slice (32 dims)
//   [34816,  43008)  u16   stok[4096]     chunk tokens
//   [43008,  59392)  u32   smask[4096]    per-token mask slice (sl 6/7 only)
//   [59392,  59456)  int   warp_part[16]
//   [59456,  59520)  int   warp_min[16]
//   [59520,  59524)  int   s_fce
#define SMEM_BYTES 59552

__global__ void __launch_bounds__(512, 3) nvm_fused_kernel(
    const float4* __restrict__ tbl4,     // [272 * 128]
    const int*    __restrict__ tok,      // [NTOK]
    float4*       __restrict__ out4)     // [NTOK * 128]
{
    extern __shared__ char smem[];
    float4* stbl     = (float4*)(smem);
    u16*    stok     = (u16*)(smem + 34816);
    u32*    smask    = (u32*)(smem + 43008);
    int*    warp_part= (int*)(smem + 59392);
    int*    warp_min = (int*)(smem + 59456);
    int*    s_fce    = (int*)(smem + 59520);

    int sl      = blockIdx.y;            // 0..15 dim slice
    int tokbase = blockIdx.x * TOKC;
    int b       = tokbase >> 13;         // batch row
    int ci      = (tokbase >> 12) & 1;   // chunk within row (0/1)
    int tid     = threadIdx.x;
    int lane    = tid & 31, wid = tid >> 5;

    // ---- stage table slice (272 rows x 8 float4) ----
#pragma unroll
    for (int i = tid; i < 272 * 8; i += 512)
        stbl[i] = __ldg(&tbl4[(i >> 3) * 128 + sl * 8 + (i & 7)]);

    // ---- stage chunk tokens as u16 ----
    {
        const int4* tok4 = (const int4*)(tok + tokbase);
        u32* st32 = (u32*)stok;
#pragma unroll
        for (int i = tid; i < TOKC / 4; i += 512) {
            int4 v = __ldg(&tok4[i]);
            st32[2 * i]     = (u32)v.x | ((u32)v.y << 16);
            st32[2 * i + 1] = (u32)v.z | ((u32)v.w << 16);
        }
    }

    // ---- slices 6/7: full-row scan + mask build into smem ----
    if (sl == 6 || sl == 7) {
        const int4* row4 = (const int4*)(tok + b * SS);
        int base = tid * 16;                 // row-relative start

        int own[16];
        {
            int4 v0 = __ldg(&row4[tid * 4 + 0]);
            int4 v1 = __ldg(&row4[tid * 4 + 1]);
            int4 v2 = __ldg(&row4[tid * 4 + 2]);
            int4 v3 = __ldg(&row4[tid * 4 + 3]);
            own[0]=v0.x; own[1]=v0.y; own[2]=v0.z; own[3]=v0.w;
            own[4]=v1.x; own[5]=v1.y; own[6]=v1.z; own[7]=v1.w;
            own[8]=v2.x; own[9]=v2.y; own[10]=v2.z; own[11]=v2.w;
            own[12]=v3.x; own[13]=v3.y; own[14]=v3.z; own[15]=v3.w;
        }

        int run = -1, lce = SS;
#pragma unroll
        for (int i = 0; i < 16; i++) {
            int t = own[i];
            if (t == 256) run = base + i;
            if (t == 257 && (base + i) < lce) lce = base + i;
        }
        // warp reduce min(lce) + warp inclusive max-scan(run)
        int e = lce;
#pragma unroll
        for (int off = 16; off > 0; off >>= 1) {
            int o = __shfl_down_sync(0xffffffffu, e, off);
            if (o < e) e = o;
        }
        int v = run;
#pragma unroll
        for (int off = 1; off < 32; off <<= 1) {
            int o = __shfl_up_sync(0xffffffffu, v, off);
            if (lane >= off && o > v) v = o;
        }
        if (lane == 0)  warp_min[wid]  = e;
        if (lane == 31) warp_part[wid] = v;
        __syncthreads();
        if (wid == 0 && lane < 16) {
            int w = warp_part[lane];
#pragma unroll
            for (int off = 1; off < 16; off <<= 1) {
                int o = __shfl_up_sync(0x0000ffffu, w, off);
                if (lane >= off && o > w) w = o;
            }
            warp_part[lane] = w;
            if (lane == 0) {
                int f = SS;
#pragma unroll
                for (int i = 0; i < 16; i++)
                    if (warp_min[i] < f) f = warp_min[i];
                *s_fce = f;
            }
        }
        __syncthreads();

        int wpre = (wid == 0) ? -1 : warp_part[wid - 1];
        int excl = __shfl_up_sync(0xffffffffu, v, 1);
        if (lane == 0) excl = -1;
        int prefix = (excl > wpre) ? excl : wpre;
        int fce = *s_fce;

        // only threads whose 16 tokens lie in this block's chunk build masks
        if ((tid >> 8) == ci) {
            int h[8];
#pragma unroll
            for (int j = 0; j < 8; j++) h[j] = -1;
            if (tid > 0) {
                int4 ha = __ldg(&row4[tid * 4 - 2]);
                int4 hb = __ldg(&row4[tid * 4 - 1]);
                h[0]=ha.x; h[1]=ha.y; h[2]=ha.z; h[3]=ha.w;
                h[4]=hb.x; h[5]=hb.y; h[6]=hb.z; h[7]=hb.w;
            }
            int cur = prefix;
            int shift = (sl == 6) ? 0 : 18;
            int mbase = base - ci * TOKC;        // chunk-relative
#pragma unroll
            for (int i = 0; i < 16; i++) {
                int s = base + i;
                int t = own[i];
                if (t == 256) cur = s;           // inclusive cummax
                u64 m = 0ull;
                // code path
                if (cur >= 0 && s < fce && t < 256) {
                    int seq = s - cur - 1;
                    int bo  = seq & 7;
                    if (seq >= 0 && bo < 5) {
                        int addr = ((seq & ~7) + 2 + bo) & 4095;
                        m |= (1ull << (addr & 15))
                           | (1ull << (16 + ((addr >> 4) & 15)))
                           | (1ull << (32 + ((addr >> 8) & 15)));
                    }
                }
                // mem look-back: j = s-5-off, window idx wi = i-5-off in [-8,10]
#pragma unroll
                for (int off = 0; off < 4; off++) {
                    int jg = s - 5 - off;
                    if (jg >= 0 && (jg + 8) < SS) {
                        const int wi = i - 5 - off;
                        int tj  = (wi   >= 0) ? own[wi]     : h[wi + 8];
                        int tj1 = (wi+1 >= 0) ? own[wi + 1] : h[wi + 9];
                        int tj2 = (wi+2 >= 0) ? own[wi + 2] : h[wi + 10];
                        if (tj == 258) {
                            int a = ((tj1 | (tj2 << 8)) + off) & 4095;
                            m |= (1ull << (a & 15))
                               | (1ull << (16 + ((a >> 4) & 15)))
                               | (1ull << (32 + ((a >> 8) & 15)));
                        }
                    }
                }
                smask[mbase + i] = (u32)(m >> shift);
            }
        }
    }
    __syncthreads();

    // ---- store phase: LDS gather -> STG.128 stream ----
    int l = tid & 7;                 // float4 lane within slice
    int g = tid >> 3;                // token group 0..63
    int glane = sl * 8 + l;
    float4* outp = out4 + (size_t)(tokbase + g) * 128 + glane;

    if (sl == 6) {
#pragma unroll 8
        for (int k = 0; k < TOKC / 64; k++) {
            int tt = g + 64 * k;
            float4 v = stbl[(int)stok[tt] * 8 + l];
            u32 mw = smask[tt];
            float* vp = (float*)&v;
#pragma unroll
            for (int c = 0; c < 4; c++) {
                int bi = 4 * l + c - 14;          // dim = 192+4l+c, bit = dim-206
                if (bi >= 0 && ((mw >> bi) & 1u)) vp[c] = 1.0f;
            }
            __stcs(outp + (size_t)(64 * k) * 128, v);
        }
    } else if (sl == 7) {
#pragma unroll 8
        for (int k = 0; k < TOKC / 64; k++) {
            int tt = g + 64 * k;
            float4 v = stbl[(int)stok[tt] * 8 + l];
            u32 mw = smask[tt];
            float* vp = (float*)&v;
#pragma unroll
            for (int c = 0; c < 4; c++) {
                int bi = 4 * l + c;               // dim = 224+4l+c, bit = dim-206-18
                if (bi < 30 && ((mw >> bi) & 1u)) vp[c] = 1.0f;
            }
            __stcs(outp + (size_t)(64 * k) * 128, v);
        }
    } else if (sl == 14) {
#pragma unroll 8
        for (int k = 0; k < TOKC / 64; k++) {
            int tt = g + 64 * k;
            int t = (int)stok[tt];
            float4 v = stbl[t * 8 + l];
            if (l == 2) {                          // dims 456..459
                int srel = (tokbase + tt) & (SS - 1);
                if (t == 259) v.x = 1.0f;                     // 456
                if (t == 260) v.y = 1.0f;                     // 457
                if (t == 258 && srel < SS - 8) v.z = 1.0f;    // 458
            }
            __stcs(outp + (size_t)(64 * k) * 128, v);
        }
    } else {
#pragma unroll 8
        for (int k = 0; k < TOKC / 64; k++) {
            int tt = g + 64 * k;
            float4 v = stbl[(int)stok[tt] * 8 + l];
            __stcs(outp + (size_t)(64 * k) * 128, v);
        }
    }
}

// ---------------------------------------------------------------------------
extern "C" void kernel_launch(void* const* d_in, const int* in_sizes, int n_in,
                              void* d_out, int out_size) {
    const float* tbl;
    const int* tok;
    if (in_sizes[0] == 272 * 512) {
        tbl = (const float*)d_in[0];
        tok = (const int*)d_in[1];
    } else {
        tbl = (const float*)d_in[1];
        tok = (const int*)d_in[0];
    }
    float* out = (float*)d_out;

    cudaFuncSetAttribute(nvm_fused_kernel,
                         cudaFuncAttributeMaxDynamicSharedMemorySize,
                         SMEM_BYTES);

    dim3 grid(NCH, SLICES);   // (16, 16) = 256 blocks, single wave
    nvm_fused_kernel<<<grid, 512, SMEM_BYTES>>>(
        (const float4*)tbl, tok, (float4*)out);
}